// round 1
// baseline (speedup 1.0000x reference)
#include <cuda_runtime.h>

// Problem constants (fixed by the reference)
#define BATCH 4
#define CHAN  256
#define HH    192
#define WW    192
#define MAXD  4
#define WIN   9          // 2*MAXD+1
#define NDISP 81         // WIN*WIN

// Tiling
#define TILE_X 32
#define TILE_Y 4
#define PX     4                 // pixels per thread along x
#define NTX    (TILE_X / PX)     // 8 threads in x
#define SROWS  (TILE_Y + 2*MAXD) // 12
#define SCOLS  (TILE_X + 2*MAXD) // 40
#define SPITCH 48                // 48 % 32 == 16 -> perfect 2-phase float4 LDS
#define FPITCH 32
#define CH     8                 // channels per sync round
#define NTHREADS (NTX * TILE_Y * WIN)  // 8*4*9 = 288

__global__ __launch_bounds__(NTHREADS, 2)
void corr_kernel(const float* __restrict__ F,
                 const float* __restrict__ S,
                 float* __restrict__ out)
{
    __shared__ float sS[CH][SROWS][SPITCH];
    __shared__ float sF[CH][TILE_Y][FPITCH];

    const int tx = threadIdx.x;            // 0..7
    const int ty = threadIdx.y;            // 0..3
    const int g  = threadIdx.z;            // 0..8  (dy index)
    const int tid = tx + NTX * ty + NTX * TILE_Y * g;

    const int tileX = blockIdx.x * TILE_X;
    const int tileY = blockIdx.y * TILE_Y;
    const int b     = blockIdx.z;

    const float* Fb = F + (size_t)b * CHAN * HH * WW;
    const float* Sb = S + (size_t)b * CHAN * HH * WW;

    float acc[PX][WIN];
#pragma unroll
    for (int p = 0; p < PX; p++)
#pragma unroll
        for (int d = 0; d < WIN; d++) acc[p][d] = 0.0f;

    const int x0 = PX * tx;  // tile-local pixel base

    for (int c0 = 0; c0 < CHAN; c0 += CH) {
        // ---- cooperative load: S tile with halo (zero padded) ----
        for (int idx = tid; idx < CH * SROWS * SCOLS; idx += NTHREADS) {
            int ch  = idx / (SROWS * SCOLS);
            int rem = idx - ch * (SROWS * SCOLS);
            int r   = rem / SCOLS;
            int cc  = rem - r * SCOLS;
            int gy = tileY + r - MAXD;
            int gx = tileX + cc - MAXD;
            float v = 0.0f;
            if (gy >= 0 && gy < HH && gx >= 0 && gx < WW)
                v = Sb[(size_t)(c0 + ch) * (HH * WW) + gy * WW + gx];
            sS[ch][r][cc] = v;
        }
        // ---- cooperative load: F tile ----
        for (int idx = tid; idx < CH * TILE_Y * TILE_X; idx += NTHREADS) {
            int ch  = idx >> 7;        // / 128
            int rem = idx & 127;
            int r   = rem >> 5;        // / 32
            int cc  = rem & 31;
            sF[ch][r][cc] = Fb[(size_t)(c0 + ch) * (HH * WW)
                               + (tileY + r) * WW + (tileX + cc)];
        }
        __syncthreads();

        // ---- accumulate: each thread = 4 pixels x 1 dy x 9 dx ----
#pragma unroll
        for (int ch = 0; ch < CH; ch++) {
            float4 f4 = *(const float4*)&sF[ch][ty][x0];
            float f[PX] = {f4.x, f4.y, f4.z, f4.w};

            const int sy = ty + g;   // S tile row for this dy
            float4 a0 = *(const float4*)&sS[ch][sy][x0];
            float4 a1 = *(const float4*)&sS[ch][sy][x0 + 4];
            float4 a2 = *(const float4*)&sS[ch][sy][x0 + 8];
            float w[PX + WIN - 1 + 0];
            float wreg[12] = {a0.x, a0.y, a0.z, a0.w,
                              a1.x, a1.y, a1.z, a1.w,
                              a2.x, a2.y, a2.z, a2.w};
            (void)w;
#pragma unroll
            for (int p = 0; p < PX; p++) {
#pragma unroll
                for (int d = 0; d < WIN; d++) {
                    acc[p][d] = fmaf(f[p], wreg[p + d], acc[p][d]);
                }
            }
        }
        __syncthreads();
    }

    // ---- store: scale by 1/C, vectorized float4 (4 consecutive x) ----
    const float inv = 1.0f / (float)CHAN;
    const int y  = tileY + ty;
    const int gx = tileX + x0;
#pragma unroll
    for (int d = 0; d < WIN; d++) {
        int disp = g * WIN + d;
        float4 v;
        v.x = acc[0][d] * inv;
        v.y = acc[1][d] * inv;
        v.z = acc[2][d] * inv;
        v.w = acc[3][d] * inv;
        *(float4*)&out[((size_t)(b * NDISP + disp) * HH + y) * WW + gx] = v;
    }
}

extern "C" void kernel_launch(void* const* d_in, const int* in_sizes, int n_in,
                              void* d_out, int out_size)
{
    const float* tensorFirst  = (const float*)d_in[0];
    const float* tensorSecond = (const float*)d_in[1];
    float* out = (float*)d_out;

    dim3 grid(WW / TILE_X, HH / TILE_Y, BATCH);   // 6 x 48 x 4
    dim3 block(NTX, TILE_Y, WIN);                 // 8 x 4 x 9 = 288
    corr_kernel<<<grid, block>>>(tensorFirst, tensorSecond, out);
}

// round 2
// speedup vs baseline: 1.9967x; 1.9967x over previous
#include <cuda_runtime.h>
#include <cstdint>

// Problem constants (fixed by the reference)
#define BATCH 4
#define CHAN  256
#define HH    192
#define WW    192
#define HW    (HH*WW)
#define MAXD  4
#define WIN   9          // 2*MAXD+1
#define NDISP 81         // WIN*WIN

// Tiling
#define TILE_X 32
#define TILE_Y 4
#define PX     4                 // pixels per thread along x
#define NTX    (TILE_X / PX)     // 8 threads in x
#define SROWS  (TILE_Y + 2*MAXD) // 12
#define SCOLS  (TILE_X + 2*MAXD) // 40 -> 10 float4 per row
#define SVEC   10                // float4s per S row
#define SPITCH 48                // 48 % 32 == 16 -> conflict-free float4 LDS
#define FPITCH 32
#define CH     8                 // channels per pipeline stage
#define NROUNDS (CHAN / CH)      // 32
#define NTHREADS (NTX * TILE_Y * WIN)  // 288

#define S_VECS (CH * SROWS * SVEC)     // 960 float4 copies per stage
#define F_VECS (CH * TILE_Y * (TILE_X/4)) // 256 float4 copies per stage

#define S_BUF_BYTES (CH * SROWS * SPITCH * 4)   // 18432
#define F_BUF_BYTES (CH * TILE_Y * FPITCH * 4)  // 4096

__device__ __forceinline__ void cp_async16(uint32_t saddr, const float* gptr, bool full)
{
    int sz = full ? 16 : 0;   // src-size 0 -> 16 bytes of zero fill (halo padding)
    asm volatile("cp.async.cg.shared.global [%0], [%1], 16, %2;\n"
                 :: "r"(saddr), "l"(gptr), "r"(sz));
}

__global__ __launch_bounds__(NTHREADS, 2)
void corr_kernel(const float* __restrict__ F,
                 const float* __restrict__ S,
                 float* __restrict__ out)
{
    __shared__ float sS[2][CH][SROWS][SPITCH];
    __shared__ float sF[2][CH][TILE_Y][FPITCH];

    const int tx = threadIdx.x;            // 0..7
    const int ty = threadIdx.y;            // 0..3
    const int g  = threadIdx.z;            // 0..8  (dy index) -> one warp per g
    const int tid = tx + NTX * ty + NTX * TILE_Y * g;

    const int tileX = blockIdx.x * TILE_X;
    const int tileY = blockIdx.y * TILE_Y;
    const int b     = blockIdx.z;

    const float* Fb = F + (size_t)b * CHAN * HW;
    const float* Sb = S + (size_t)b * CHAN * HW;

    // ---------------- precompute load roles (done once) ----------------
    // S tile: 960 float4 copies/stage -> roles k=0..2 for all threads, k=3 for tid<96
    const float* s_ptr[4];
    uint32_t     s_smem[4];
    bool         s_pred[4];
#pragma unroll
    for (int k = 0; k < 4; k++) {
        int v   = tid + k * NTHREADS;
        int ch  = v / (SROWS * SVEC);
        int rem = v - ch * (SROWS * SVEC);
        int row = rem / SVEC;
        int c4  = rem - row * SVEC;
        int gy  = tileY + row - MAXD;
        int gx  = tileX + c4 * 4 - MAXD;
        bool inb = (gy >= 0) && (gy < HH) && (gx >= 0) && (gx + 4 <= WW);
        s_pred[k] = inb;
        s_ptr[k]  = Sb + (size_t)ch * HW + (inb ? (gy * WW + gx) : 0);
        s_smem[k] = (uint32_t)__cvta_generic_to_shared(&sS[0][ch][row][c4 * 4]);
    }
    // F tile: 256 float4 copies/stage -> tid<256 one each
    const float* f_ptr = Fb;
    uint32_t     f_smem = 0;
    {
        int t   = (tid < F_VECS) ? tid : 0;
        int ch  = t >> 5;
        int rem = t & 31;
        int row = rem >> 3;
        int c4  = rem & 7;
        f_ptr  = Fb + (size_t)ch * HW + (tileY + row) * WW + tileX + c4 * 4;
        f_smem = (uint32_t)__cvta_generic_to_shared(&sF[0][ch][row][c4 * 4]);
    }

    // ---------------- pipelined load issue ----------------
    auto issue = [&](int r) {
        uint32_t sOff = (r & 1) ? (uint32_t)S_BUF_BYTES : 0u;
        uint32_t fOff = (r & 1) ? (uint32_t)F_BUF_BYTES : 0u;
        size_t   cOff = (size_t)r * CH * HW;
#pragma unroll
        for (int k = 0; k < 4; k++) {
            if (k < 3 || tid < (S_VECS - 3 * NTHREADS)) {
                cp_async16(s_smem[k] + sOff, s_ptr[k] + cOff, s_pred[k]);
            }
        }
        if (tid < F_VECS) cp_async16(f_smem + fOff, f_ptr + cOff, true);
        asm volatile("cp.async.commit_group;\n" ::: "memory");
    };

    float acc[PX][WIN];
#pragma unroll
    for (int p = 0; p < PX; p++)
#pragma unroll
        for (int d = 0; d < WIN; d++) acc[p][d] = 0.0f;

    const int x0 = PX * tx;
    const int sy = ty + g;

    issue(0);

    for (int r = 0; r < NROUNDS; r++) {
        asm volatile("cp.async.wait_group 0;\n" ::: "memory");
        __syncthreads();                        // round r data visible to all;
                                                // buf[(r+1)&1] readers (round r-1) all done
        if (r + 1 < NROUNDS) issue(r + 1);      // stream next stage during compute

        const int bb = r & 1;
#pragma unroll
        for (int ch = 0; ch < CH; ch++) {
            float4 f4 = *(const float4*)&sF[bb][ch][ty][x0];
            float4 a0 = *(const float4*)&sS[bb][ch][sy][x0];
            float4 a1 = *(const float4*)&sS[bb][ch][sy][x0 + 4];
            float4 a2 = *(const float4*)&sS[bb][ch][sy][x0 + 8];
            float f[PX]  = {f4.x, f4.y, f4.z, f4.w};
            float w[12]  = {a0.x, a0.y, a0.z, a0.w,
                            a1.x, a1.y, a1.z, a1.w,
                            a2.x, a2.y, a2.z, a2.w};
#pragma unroll
            for (int p = 0; p < PX; p++) {
#pragma unroll
                for (int d = 0; d < WIN; d++) {
                    acc[p][d] = fmaf(f[p], w[p + d], acc[p][d]);
                }
            }
        }
        // no trailing barrier: next iteration's (wait_group + __syncthreads)
        // orders compute(r) before any overwrite of buf[r&1] (which first
        // happens in issue(r+2), after that barrier)
    }

    // ---------------- store: scale by 1/C, float4 ----------------
    const float inv = 1.0f / (float)CHAN;
    const int y  = tileY + ty;
    const int gx = tileX + x0;
#pragma unroll
    for (int d = 0; d < WIN; d++) {
        int disp = g * WIN + d;
        float4 v;
        v.x = acc[0][d] * inv;
        v.y = acc[1][d] * inv;
        v.z = acc[2][d] * inv;
        v.w = acc[3][d] * inv;
        *(float4*)&out[((size_t)(b * NDISP + disp) * HH + y) * WW + gx] = v;
    }
}

extern "C" void kernel_launch(void* const* d_in, const int* in_sizes, int n_in,
                              void* d_out, int out_size)
{
    const float* tensorFirst  = (const float*)d_in[0];
    const float* tensorSecond = (const float*)d_in[1];
    float* out = (float*)d_out;

    dim3 grid(WW / TILE_X, HH / TILE_Y, BATCH);   // 6 x 48 x 4
    dim3 block(NTX, TILE_Y, WIN);                 // 8 x 4 x 9 = 288
    corr_kernel<<<grid, block>>>(tensorFirst, tensorSecond, out);
}

// round 3
// speedup vs baseline: 2.6736x; 1.3390x over previous
#include <cuda_runtime.h>
#include <cstdint>

// Problem constants (fixed by the reference)
#define BATCH 4
#define CHAN  256
#define HH    192
#define WW    192
#define HW    (HH*WW)
#define MAXD  4
#define WIN   9
#define NDISP 81

// Tiling
#define TILE_X 32
#define TILE_Y 4
#define PX     8                 // pixels per thread along x
#define NTX    (TILE_X / PX)     // 4
#define SROWS  (TILE_Y + 2*MAXD) // 12
#define SCOLS  (TILE_X + 2*MAXD) // 40 -> 10 float4 per row
#define SVEC   10
#define SPITCH 48                // floats; 192B row stride
#define FPITCH 36                // floats; 144B row stride (banks rotate per row)
#define CH     8
#define NROUNDS (CHAN / CH)      // 32
#define NTHREADS (NTX * TILE_Y * WIN)  // 4*4*9 = 144

#define S_VECS (CH * SROWS * SVEC)        // 960 float4 per stage
#define F_VECS (CH * TILE_Y * (TILE_X/4)) // 256 float4 per stage
#define S_ROLES 7                          // ceil(960/144): 6 full + 96
#define F_ROLES 2                          // 144 + 112

#define S_BUF_BYTES (CH * SROWS * SPITCH * 4)   // 18432
#define F_BUF_BYTES (CH * TILE_Y * FPITCH * 4)  // 4608

typedef unsigned long long u64;

__device__ __forceinline__ void cp_async16(uint32_t saddr, const float* gptr, bool full)
{
    int sz = full ? 16 : 0;   // src-size 0 -> 16B zero fill (halo)
    asm volatile("cp.async.cg.shared.global [%0], [%1], 16, %2;\n"
                 :: "r"(saddr), "l"(gptr), "r"(sz));
}

__device__ __forceinline__ u64 pk(float lo, float hi)
{
    u64 v;
    asm("mov.b64 %0, {%1, %2};" : "=l"(v) : "f"(lo), "f"(hi));
    return v;
}

__device__ __forceinline__ void ffma2(u64& acc, u64 a, u64 b)
{
    asm("fma.rn.f32x2 %0, %1, %2, %3;" : "=l"(acc) : "l"(a), "l"(b), "l"(acc));
}

__device__ __forceinline__ void unpk(u64 v, float& lo, float& hi)
{
    asm("mov.b64 {%0, %1}, %2;" : "=f"(lo), "=f"(hi) : "l"(v));
}

__global__ __launch_bounds__(NTHREADS, 3)
void corr_kernel(const float* __restrict__ F,
                 const float* __restrict__ S,
                 float* __restrict__ out)
{
    __shared__ float sS[2][CH][SROWS][SPITCH];
    __shared__ float sF[2][CH][TILE_Y][FPITCH];

    const int tx = threadIdx.x;            // 0..3
    const int ty = threadIdx.y;            // 0..3
    const int g  = threadIdx.z;            // 0..8 (dy)
    const int tid = tx + NTX * ty + NTX * TILE_Y * g;

    const int tileX = blockIdx.x * TILE_X;
    const int tileY = blockIdx.y * TILE_Y;
    const int b     = blockIdx.z;

    const float* Fb = F + (size_t)b * CHAN * HW;
    const float* Sb = S + (size_t)b * CHAN * HW;

    // ---------------- precompute load roles ----------------
    const float* s_ptr[S_ROLES];
    uint32_t     s_smem[S_ROLES];
    bool         s_pred[S_ROLES];
#pragma unroll
    for (int k = 0; k < S_ROLES; k++) {
        int v   = tid + k * NTHREADS;
        if (v >= S_VECS) v = 0;            // inactive role; predicated off at issue
        int ch  = v / (SROWS * SVEC);
        int rem = v - ch * (SROWS * SVEC);
        int row = rem / SVEC;
        int c4  = rem - row * SVEC;
        int gy  = tileY + row - MAXD;
        int gx  = tileX + c4 * 4 - MAXD;
        bool inb = (gy >= 0) && (gy < HH) && (gx >= 0) && (gx + 4 <= WW);
        s_pred[k] = inb;
        s_ptr[k]  = Sb + (size_t)ch * HW + (inb ? (gy * WW + gx) : 0);
        s_smem[k] = (uint32_t)__cvta_generic_to_shared(&sS[0][ch][row][c4 * 4]);
    }
    const float* f_ptr[F_ROLES];
    uint32_t     f_smem[F_ROLES];
#pragma unroll
    for (int k = 0; k < F_ROLES; k++) {
        int v   = tid + k * NTHREADS;
        if (v >= F_VECS) v = 0;
        int ch  = v >> 5;                  // /32 (8 float4 per row * 4 rows)
        int rem = v & 31;
        int row = rem >> 3;
        int c4  = rem & 7;
        f_ptr[k]  = Fb + (size_t)ch * HW + (tileY + row) * WW + tileX + c4 * 4;
        f_smem[k] = (uint32_t)__cvta_generic_to_shared(&sF[0][ch][row][c4 * 4]);
    }

    auto issue = [&](int r) {
        uint32_t sOff = (r & 1) ? (uint32_t)S_BUF_BYTES : 0u;
        uint32_t fOff = (r & 1) ? (uint32_t)F_BUF_BYTES : 0u;
        size_t   cOff = (size_t)r * CH * HW;
#pragma unroll
        for (int k = 0; k < S_ROLES; k++) {
            if (k < 6 || tid < (S_VECS - 6 * NTHREADS)) {
                cp_async16(s_smem[k] + sOff, s_ptr[k] + cOff, s_pred[k]);
            }
        }
#pragma unroll
        for (int k = 0; k < F_ROLES; k++) {
            if (k < 1 || tid < (F_VECS - NTHREADS)) {
                cp_async16(f_smem[k] + fOff, f_ptr[k] + cOff, true);
            }
        }
        asm volatile("cp.async.commit_group;\n" ::: "memory");
    };

    // accumulators: 4 pixel-pairs x 9 dx, packed f32x2
    u64 A[4][WIN];
#pragma unroll
    for (int q = 0; q < 4; q++)
#pragma unroll
        for (int d = 0; d < WIN; d++) A[q][d] = 0ull;

    const int x0 = PX * tx;      // 0,8,16,24
    const int sy = ty + g;

    issue(0);

    for (int r = 0; r < NROUNDS; r++) {
        asm volatile("cp.async.wait_group 0;\n" ::: "memory");
        __syncthreads();
        if (r + 1 < NROUNDS) issue(r + 1);

        const int bb = r & 1;
#pragma unroll
        for (int ch = 0; ch < CH; ch++) {
            const float* fr = &sF[bb][ch][ty][x0];
            float4 f0 = *(const float4*)fr;
            float4 f1 = *(const float4*)(fr + 4);
            u64 fp[4] = { pk(f0.x, f0.y), pk(f0.z, f0.w),
                          pk(f1.x, f1.y), pk(f1.z, f1.w) };

            const float* wr = &sS[bb][ch][sy][x0];
            float4 w0 = *(const float4*)wr;
            float4 w1 = *(const float4*)(wr + 4);
            float4 w2 = *(const float4*)(wr + 8);
            float4 w3 = *(const float4*)(wr + 12);
            float w[16] = { w0.x, w0.y, w0.z, w0.w,
                            w1.x, w1.y, w1.z, w1.w,
                            w2.x, w2.y, w2.z, w2.w,
                            w3.x, w3.y, w3.z, w3.w };
            u64 wp[15];
#pragma unroll
            for (int j = 0; j < 15; j++) wp[j] = pk(w[j], w[j + 1]);

#pragma unroll
            for (int q = 0; q < 4; q++) {       // pixel pair (2q, 2q+1)
#pragma unroll
                for (int d = 0; d < WIN; d++) {
                    ffma2(A[q][d], fp[q], wp[2 * q + d]);
                }
            }
        }
    }

    // ---------------- store: scale by 1/C ----------------
    const float inv = 1.0f / (float)CHAN;
    const int y  = tileY + ty;
    const int gx = tileX + x0;
#pragma unroll
    for (int d = 0; d < WIN; d++) {
        int disp = g * WIN + d;
        float p0, p1, p2, p3, p4, p5, p6, p7;
        unpk(A[0][d], p0, p1);
        unpk(A[1][d], p2, p3);
        unpk(A[2][d], p4, p5);
        unpk(A[3][d], p6, p7);
        float4 v0 = { p0 * inv, p1 * inv, p2 * inv, p3 * inv };
        float4 v1 = { p4 * inv, p5 * inv, p6 * inv, p7 * inv };
        float* o = &out[((size_t)(b * NDISP + disp) * HH + y) * WW + gx];
        *(float4*)o       = v0;
        *(float4*)(o + 4) = v1;
    }
}

extern "C" void kernel_launch(void* const* d_in, const int* in_sizes, int n_in,
                              void* d_out, int out_size)
{
    const float* tensorFirst  = (const float*)d_in[0];
    const float* tensorSecond = (const float*)d_in[1];
    float* out = (float*)d_out;

    dim3 grid(WW / TILE_X, HH / TILE_Y, BATCH);   // 6 x 48 x 4
    dim3 block(NTX, TILE_Y, WIN);                 // 4 x 4 x 9 = 144
    corr_kernel<<<grid, block>>>(tensorFirst, tensorSecond, out);
}